// round 15
// baseline (speedup 1.0000x reference)
#include <cuda_runtime.h>
#include <cuda_fp16.h>
#include <stdint.h>
#include <math.h>

#define B_  2
#define S_  2048
#define D_  1024
#define H_  16
#define HD_ 64

// Scratch (allocation-free rule: __device__ globals).
// g_xh: fp16 copies of queries/keys/values, [which][B][S][D].
// g_wh: fp16 TRANSPOSED weights, [which][H][HD][D]  (n-major rows of k).
// g_q:  fp16 [bh][seq][dim], pre-scaled by 1/sqrt(HD). g_k: fp16 [bh][seq][dim].
// g_v:  fp16 TRANSPOSED [bh][dim][seq] (PV mma wants V as [dim][key]).
__device__ __half g_xh[(size_t)3 * B_ * S_ * D_];
__device__ __half g_wh[(size_t)3 * H_ * D_ * HD_];
__device__ __half g_q[(size_t)B_ * H_ * S_ * HD_];
__device__ __half g_k[(size_t)B_ * H_ * S_ * HD_];
__device__ __half g_v[(size_t)B_ * H_ * S_ * HD_];
__device__ float  g_att[(size_t)B_ * S_ * D_];

__device__ __forceinline__ void mma_f16(float* c, const uint32_t* a, uint32_t b0, uint32_t b1) {
    asm volatile(
        "mma.sync.aligned.m16n8k16.row.col.f32.f16.f16.f32 "
        "{%0,%1,%2,%3}, {%4,%5,%6,%7}, {%8,%9}, {%0,%1,%2,%3};"
        : "+f"(c[0]), "+f"(c[1]), "+f"(c[2]), "+f"(c[3])
        : "r"(a[0]), "r"(a[1]), "r"(a[2]), "r"(a[3]), "r"(b0), "r"(b1));
}

__device__ __forceinline__ uint32_t pack_h2(float lo, float hi) {
    __half2 h = __floats2half2_rn(lo, hi);
    return *(uint32_t*)&h;
}

#define CP_ASYNC16(saddr, gptr) \
    asm volatile("cp.async.cg.shared.global [%0], [%1], 16;\n" :: "r"(saddr), "l"(gptr))
#define CP_COMMIT() asm volatile("cp.async.commit_group;\n" ::: "memory")
#define CP_WAIT0()  asm volatile("cp.async.wait_group 0;\n" ::: "memory")

// ============================================================================
// Pre-convert X (queries/keys/values) to fp16, flat copy. grid (2048, 3).
// ============================================================================
__global__ __launch_bounds__(256) void convx_kernel(
    const float* __restrict__ Xq, const float* __restrict__ Xk, const float* __restrict__ Xv)
{
    const int which = blockIdx.y;
    const float* X = (which == 0) ? Xq : (which == 1) ? Xk : Xv;
    __half* out = g_xh + (size_t)which * B_ * S_ * D_;

    size_t i = ((size_t)blockIdx.x * 256 + threadIdx.x);     // 8 elems each
    const float4* src = (const float4*)X;
    float4 v0 = src[2 * i];
    float4 v1 = src[2 * i + 1];
    uint4 o = make_uint4(pack_h2(v0.x, v0.y), pack_h2(v0.z, v0.w),
                         pack_h2(v1.x, v1.y), pack_h2(v1.z, v1.w));
    ((uint4*)out)[i] = o;
}

// ============================================================================
// Pre-convert + transpose W: [h][k=D][n=HD] fp32 -> [h][n=HD][k=D] fp16.
// Standard smem 32x32 tile transpose. grid (D/32, HD/32, 3*H), block (32,8).
// ============================================================================
__global__ void convw_kernel(
    const float* __restrict__ Wq, const float* __restrict__ Wk, const float* __restrict__ Wv)
{
    const int which = blockIdx.z / H_;
    const int h     = blockIdx.z % H_;
    const float* W = ((which == 0) ? Wq : (which == 1) ? Wk : Wv) + (size_t)h * D_ * HD_;
    __half* out = g_wh + ((size_t)which * H_ + h) * HD_ * D_;

    __shared__ float tile[32][33];
    const int k0 = blockIdx.x * 32;
    const int n0 = blockIdx.y * 32;
    const int tx = threadIdx.x, ty = threadIdx.y;

    #pragma unroll
    for (int i = 0; i < 4; i++)
        tile[ty + i * 8][tx] = W[(size_t)(k0 + ty + i * 8) * HD_ + n0 + tx];
    __syncthreads();
    #pragma unroll
    for (int i = 0; i < 4; i++)
        out[(size_t)(n0 + ty + i * 8) * D_ + k0 + tx] =
            __float2half_rn(tile[tx][ty + i * 8]);
}

// ============================================================================
// fp16 QKV projection: out[b,h,s,:] = fp16((Xh @ Wh[h]^T + bias[h]) * sc)
// grid = (S/128, B*(H/2), 3). Block tile M=128 x N=128 (two heads), 256 thr
// (8 warps, 2Mx4N), warp tile 64x32. m16n8k16 fp16 mma, fp32 accum.
// A: [128m][64k] fp16 stride 36 words; W: [128n][64k] fp16 stride 36 words.
// cp.async double buffer over 64-k chunks (16 chunks).
// Tiles are 128 rows x 8 sixteen-byte granules = 1024 granules -> 4 loader
// iterations of 256 threads (R13 bug: only 2 -> half the tile uninitialized).
// ============================================================================
#define PH_TILE (128 * 36)                       // words, A or W tile
#define PH_A    0
#define PH_W    (2 * PH_TILE)
#define PROJ_SMEM_WORDS (PH_W + 2 * PH_TILE)     // 18432
#define PROJ_SMEM_BYTES (PROJ_SMEM_WORDS * 4)    // 73728

__global__ __launch_bounds__(256) void proj_kernel(
    const float* __restrict__ bq, const float* __restrict__ bk, const float* __restrict__ bv)
{
    extern __shared__ uint32_t dyn[];

    const int which = blockIdx.z;
    const float* bias = (which == 0) ? bq : (which == 1) ? bk : bv;
    __half* out       = (which == 0) ? g_q : (which == 1) ? g_k : g_v;
    const float sc    = (which == 0) ? 0.125f : 1.0f;

    const int mt = blockIdx.x;           // 0..15  (S/128)
    const int bp = blockIdx.y;           // 0..15  (B * H/2)
    const int b  = bp >> 3;
    const int h0 = (bp & 7) * 2;         // first of two heads

    const __half* Xb = g_xh + ((size_t)which * B_ + b) * S_ * D_;
    const __half* Wt = g_wh + (size_t)which * H_ * HD_ * D_;   // [h][n][k]

    const int tid  = threadIdx.x;
    const int warp = tid >> 5;
    const int lane = tid & 31;
    const int g    = lane >> 2;
    const int t    = lane & 3;
    const int wm   = warp >> 2;          // 0..1 -> rows wm*64
    const int wn   = warp & 3;           // 0..3 -> cols wn*32

    const uint32_t sbase = (uint32_t)__cvta_generic_to_shared(dyn);

    float acc[4][4][4];
    #pragma unroll
    for (int ag = 0; ag < 4; ag++)
        #pragma unroll
        for (int j = 0; j < 4; j++)
            #pragma unroll
            for (int r = 0; r < 4; r++)
                acc[ag][j][r] = 0.0f;

    // Loaders: A and W tiles are both 128 rows x 8 granules (16B) = 1024
    auto issue_stage = [&](int k0, int buf) {
        uint32_t adst = sbase + (PH_A + buf * PH_TILE) * 4;
        #pragma unroll
        for (int i = 0; i < 4; i++) {
            int gid = i * 256 + tid;             // 0..1023
            int row = gid >> 3, c = gid & 7;
            CP_ASYNC16(adst + (row * 36) * 4 + c * 16,
                       Xb + (size_t)(mt * 128 + row) * D_ + k0 + c * 8);
        }
        uint32_t wdst = sbase + (PH_W + buf * PH_TILE) * 4;
        #pragma unroll
        for (int i = 0; i < 4; i++) {
            int gid = i * 256 + tid;
            int row = gid >> 3, c = gid & 7;     // row = block-n 0..127
            int h  = h0 + (row >> 6);
            int nn = row & 63;
            CP_ASYNC16(wdst + (row * 36) * 4 + c * 16,
                       Wt + ((size_t)h * HD_ + nn) * D_ + k0 + c * 8);
        }
        CP_COMMIT();
    };

    issue_stage(0, 0);

    const int NK = D_ / 64;                       // 16 chunks
    for (int kc = 0; kc < NK; kc++) {
        const int buf = kc & 1;
        CP_WAIT0();
        __syncthreads();

        if (kc + 1 < NK) issue_stage((kc + 1) * 64, buf ^ 1);

        const uint32_t* As = dyn + PH_A + buf * PH_TILE;   // [128][36]
        const uint32_t* Ws = dyn + PH_W + buf * PH_TILE;   // [128][36]

        #pragma unroll
        for (int kb = 0; kb < 4; kb++) {          // 4 x k16
            uint32_t a[4][4];
            #pragma unroll
            for (int ag = 0; ag < 4; ag++) {
                int m = wm * 64 + ag * 16;
                a[ag][0] = As[(m + g    ) * 36 + kb * 8 + t];
                a[ag][1] = As[(m + g + 8) * 36 + kb * 8 + t];
                a[ag][2] = As[(m + g    ) * 36 + kb * 8 + 4 + t];
                a[ag][3] = As[(m + g + 8) * 36 + kb * 8 + 4 + t];
            }
            uint32_t bb[4][2];
            #pragma unroll
            for (int j = 0; j < 4; j++) {
                int n = wn * 32 + j * 8;
                bb[j][0] = Ws[(n + g) * 36 + kb * 8 + t];
                bb[j][1] = Ws[(n + g) * 36 + kb * 8 + 4 + t];
            }
            #pragma unroll
            for (int ag = 0; ag < 4; ag++)
                #pragma unroll
                for (int j = 0; j < 4; j++)
                    mma_f16(acc[ag][j], a[ag], bb[j][0], bb[j][1]);
        }
        __syncthreads();
    }

    // Epilogue: add bias, scale, round to fp16.
    // Q/K: [bh][seq][dim]; V: transposed [bh][dim][seq].
    #pragma unroll
    for (int ag = 0; ag < 4; ag++) {
        int row = mt * 128 + wm * 64 + ag * 16 + g;
        #pragma unroll
        for (int j = 0; j < 4; j++) {
            int col = wn * 32 + j * 8 + 2 * t;           // 0..126 (even)
            int h   = h0 + (col >> 6);
            int ck  = col & 63;
            const float* bi = bias + (size_t)h * HD_;
            float b0 = bi[ck], b1 = bi[ck + 1];
            float v00 = (acc[ag][j][0] + b0) * sc;
            float v01 = (acc[ag][j][1] + b1) * sc;
            float v10 = (acc[ag][j][2] + b0) * sc;
            float v11 = (acc[ag][j][3] + b1) * sc;
            if (which < 2) {
                __half* Ob = out + (size_t)(b * H_ + h) * S_ * HD_;
                *(uint32_t*)&Ob[(size_t)row * HD_ + ck]       = pack_h2(v00, v01);
                *(uint32_t*)&Ob[(size_t)(row + 8) * HD_ + ck] = pack_h2(v10, v11);
            } else {
                __half* Ob = out + (size_t)(b * H_ + h) * HD_ * S_;
                Ob[(size_t)ck       * S_ + row]     = __float2half_rn(v00);
                Ob[(size_t)(ck + 1) * S_ + row]     = __float2half_rn(v01);
                Ob[(size_t)ck       * S_ + row + 8] = __float2half_rn(v10);
                Ob[(size_t)(ck + 1) * S_ + row + 8] = __float2half_rn(v11);
            }
        }
    }
}

// ============================================================================
// Flash attention, fp16 mma (m16n8k16) — MEASURED at ~150us in the 371us run;
// unchanged. One block = (b,h, 128-row Q tile), 128 threads (4 warps),
// warp owns 32 q-rows. K/V double-buffered cp.async. Static smem 29696 B.
// ============================================================================
#define KS_TILE 1152            // 32*36 words
#define VT_TILE 1280            // 64*20 words
#define KS_OFF  0
#define VT_OFF  (2 * KS_TILE)                   // 2304
#define PS_OFF  (VT_OFF + 2 * VT_TILE)          // 4864
#define ATTN_SMEM_WORDS (PS_OFF + 128 * 20)     // 7424 (29696 B)

__global__ __launch_bounds__(128) void attn_kernel()
{
    __shared__ uint32_t dyn[ATTN_SMEM_WORDS];

    const int qt = blockIdx.x;          // 0..15 (S/128)
    const int bh = blockIdx.y;          // 0..31
    const int b  = bh >> 4;
    const int h  = bh & 15;
    const int q0 = qt * 128;

    const __half* Kg = g_k + (size_t)bh * S_ * HD_;          // [seq][dim]
    const __half* Vt = g_v + (size_t)bh * HD_ * S_;          // [dim][seq]
    const uint32_t* Qu = (const uint32_t*)(g_q + (size_t)bh * S_ * HD_);

    uint32_t* Ps = dyn + PS_OFF;        // [128][20]

    const int tid  = threadIdx.x;
    const int warp = tid >> 5;          // 0..3
    const int lane = tid & 31;
    const int g    = lane >> 2;
    const int t    = lane & 3;
    const int wrow = warp * 32;

    const uint32_t sbase = (uint32_t)__cvta_generic_to_shared(dyn);

    // Q fragments: fp16 pairs, 4 k-chunks of 16 dims
    uint32_t q[2][4][4];
    #pragma unroll
    for (int grp = 0; grp < 2; grp++) {
        int r0 = q0 + wrow + grp * 16 + g;
        #pragma unroll
        for (int kb = 0; kb < 4; kb++) {
            q[grp][kb][0] = Qu[(size_t)r0 * 32 + kb * 8 + t];
            q[grp][kb][1] = Qu[(size_t)(r0 + 8) * 32 + kb * 8 + t];
            q[grp][kb][2] = Qu[(size_t)r0 * 32 + kb * 8 + 4 + t];
            q[grp][kb][3] = Qu[(size_t)(r0 + 8) * 32 + kb * 8 + 4 + t];
        }
    }

    float o[2][8][4];
    #pragma unroll
    for (int grp = 0; grp < 2; grp++)
        #pragma unroll
        for (int j = 0; j < 8; j++)
            #pragma unroll
            for (int r = 0; r < 4; r++) o[grp][j][r] = 0.0f;
    float m[4] = {-INFINITY, -INFINITY, -INFINITY, -INFINITY};
    float l[4] = {0.0f, 0.0f, 0.0f, 0.0f};

    auto load_tile = [&](int kt, int buf) {
        #pragma unroll
        for (int i = 0; i < 2; i++) {
            int gid = i * 128 + tid;
            int row = gid >> 3, c8 = gid & 7;
            CP_ASYNC16(sbase + (KS_OFF + buf * KS_TILE + row * 36) * 4 + c8 * 16,
                       Kg + (size_t)(kt * 32 + row) * HD_ + c8 * 8);
        }
        #pragma unroll
        for (int i = 0; i < 2; i++) {
            int gid = i * 128 + tid;
            int dim = gid >> 2, c8 = gid & 3;
            CP_ASYNC16(sbase + (VT_OFF + buf * VT_TILE + dim * 20) * 4 + c8 * 16,
                       Vt + (size_t)dim * S_ + kt * 32 + c8 * 8);
        }
        CP_COMMIT();
    };

    load_tile(0, 0);

    const int NT = S_ / 32;
    for (int kt = 0; kt < NT; kt++) {
        const int buf = kt & 1;
        CP_WAIT0();
        __syncthreads();                // all warps done with buf^1 from kt-1

        if (kt + 1 < NT) load_tile(kt + 1, buf ^ 1);

        const uint32_t* KsB = dyn + KS_OFF + buf * KS_TILE;   // [32][36]
        const uint32_t* VtB = dyn + VT_OFF + buf * VT_TILE;   // [64][20]

        // S = Q K^T : 32 q-rows x 32 keys per warp (4 k16-chunks)
        float s[2][4][4];
        #pragma unroll
        for (int grp = 0; grp < 2; grp++)
            #pragma unroll
            for (int j = 0; j < 4; j++)
                #pragma unroll
                for (int r = 0; r < 4; r++) s[grp][j][r] = 0.0f;

        #pragma unroll
        for (int kb = 0; kb < 4; kb++) {
            #pragma unroll
            for (int j = 0; j < 4; j++) {
                uint32_t b0 = KsB[(j * 8 + g) * 36 + kb * 8 + t];
                uint32_t b1 = KsB[(j * 8 + g) * 36 + kb * 8 + 4 + t];
                mma_f16(s[0][j], q[0][kb], b0, b1);
                mma_f16(s[1][j], q[1][kb], b0, b1);
            }
        }

        // Online softmax per 16-row group (warp-local shuffles)
        #pragma unroll
        for (int grp = 0; grp < 2; grp++) {
            const int i0 = grp * 2, i1 = grp * 2 + 1;
            float mx0 = -INFINITY, mx1 = -INFINITY;
            #pragma unroll
            for (int j = 0; j < 4; j++) {
                mx0 = fmaxf(mx0, fmaxf(s[grp][j][0], s[grp][j][1]));
                mx1 = fmaxf(mx1, fmaxf(s[grp][j][2], s[grp][j][3]));
            }
            mx0 = fmaxf(mx0, __shfl_xor_sync(0xffffffff, mx0, 1));
            mx0 = fmaxf(mx0, __shfl_xor_sync(0xffffffff, mx0, 2));
            mx1 = fmaxf(mx1, __shfl_xor_sync(0xffffffff, mx1, 1));
            mx1 = fmaxf(mx1, __shfl_xor_sync(0xffffffff, mx1, 2));

            float mn0 = fmaxf(m[i0], mx0), mn1 = fmaxf(m[i1], mx1);
            float al0 = __expf(m[i0] - mn0), al1 = __expf(m[i1] - mn1);
            m[i0] = mn0; m[i1] = mn1;

            float sum0 = 0.0f, sum1 = 0.0f;
            int rp = wrow + grp * 16 + g;
            #pragma unroll
            for (int j = 0; j < 4; j++) {
                float p00 = __expf(s[grp][j][0] - mn0);
                float p01 = __expf(s[grp][j][1] - mn0);
                float p10 = __expf(s[grp][j][2] - mn1);
                float p11 = __expf(s[grp][j][3] - mn1);
                sum0 += p00 + p01;
                sum1 += p10 + p11;
                Ps[rp * 20 + j * 4 + t]       = pack_h2(p00, p01);
                Ps[(rp + 8) * 20 + j * 4 + t] = pack_h2(p10, p11);
            }
            sum0 += __shfl_xor_sync(0xffffffff, sum0, 1);
            sum0 += __shfl_xor_sync(0xffffffff, sum0, 2);
            sum1 += __shfl_xor_sync(0xffffffff, sum1, 1);
            sum1 += __shfl_xor_sync(0xffffffff, sum1, 2);
            l[i0] = l[i0] * al0 + sum0;
            l[i1] = l[i1] * al1 + sum1;

            #pragma unroll
            for (int j = 0; j < 8; j++) {
                o[grp][j][0] *= al0; o[grp][j][1] *= al0;
                o[grp][j][2] *= al1; o[grp][j][3] *= al1;
            }
        }
        __syncwarp();   // Ps rows are warp-private; order writes before reads

        // O += P V : 2 k16-chunks over 32 keys, 8 n-blocks over 64 dims
        #pragma unroll
        for (int kb = 0; kb < 2; kb++) {
            uint32_t a0[4], a1[4];
            {
                int rp = wrow + g;
                a0[0] = Ps[rp * 20 + kb * 8 + t];
                a0[1] = Ps[(rp + 8) * 20 + kb * 8 + t];
                a0[2] = Ps[rp * 20 + kb * 8 + 4 + t];
                a0[3] = Ps[(rp + 8) * 20 + kb * 8 + 4 + t];
                rp = wrow + 16 + g;
                a1[0] = Ps[rp * 20 + kb * 8 + t];
                a1[1] = Ps[(rp + 8) * 20 + kb * 8 + t];
                a1[2] = Ps[rp * 20 + kb * 8 + 4 + t];
                a1[3] = Ps[(rp + 8) * 20 + kb * 8 + 4 + t];
            }
            #pragma unroll
            for (int j = 0; j < 8; j++) {
                uint32_t b0 = VtB[(j * 8 + g) * 20 + kb * 8 + t];
                uint32_t b1 = VtB[(j * 8 + g) * 20 + kb * 8 + 4 + t];
                mma_f16(o[0][j], a0, b0, b1);
                mma_f16(o[1][j], a1, b0, b1);
            }
        }
    }

    // Epilogue: normalize, scatter into [B,S,D] (concat heads), fp32
    float inv[4] = {1.0f / l[0], 1.0f / l[1], 1.0f / l[2], 1.0f / l[3]};
    #pragma unroll
    for (int grp = 0; grp < 2; grp++) {
        #pragma unroll
        for (int j = 0; j < 8; j++) {
            int srow = q0 + wrow + grp * 16 + g;
            int col  = h * HD_ + j * 8 + 2 * t;
            *(float2*)&g_att[((size_t)b * S_ + srow) * D_ + col] =
                make_float2(o[grp][j][0] * inv[grp * 2], o[grp][j][1] * inv[grp * 2]);
            *(float2*)&g_att[((size_t)b * S_ + srow + 8) * D_ + col] =
                make_float2(o[grp][j][2] * inv[grp * 2 + 1], o[grp][j][3] * inv[grp * 2 + 1]);
        }
    }
}

// ============================================================================
// LayerNorm over last dim (1024). One block (256 thr) per row; float4 I/O.
// ============================================================================
__global__ __launch_bounds__(256) void ln_kernel(const float* __restrict__ gamma,
                                                 const float* __restrict__ beta,
                                                 float* __restrict__ out)
{
    const int row = blockIdx.x;
    const float* x = g_att + (size_t)row * D_;
    float*       y = out   + (size_t)row * D_;

    const int tid = threadIdx.x;
    float4 v = *(const float4*)&x[tid * 4];
    float sum = v.x + v.y + v.z + v.w;
    float sq  = v.x * v.x + v.y * v.y + v.z * v.z + v.w * v.w;

    #pragma unroll
    for (int off = 16; off > 0; off >>= 1) {
        sum += __shfl_down_sync(0xffffffff, sum, off);
        sq  += __shfl_down_sync(0xffffffff, sq,  off);
    }
    __shared__ float rs[8], rq[8], stats[2];
    int warp = tid >> 5, lane = tid & 31;
    if (lane == 0) { rs[warp] = sum; rq[warp] = sq; }
    __syncthreads();
    if (tid == 0) {
        float ts = 0.0f, tq = 0.0f;
        #pragma unroll
        for (int i = 0; i < 8; i++) { ts += rs[i]; tq += rq[i]; }
        float mean = ts * (1.0f / D_);
        float var  = tq * (1.0f / D_) - mean * mean;
        stats[0] = mean;
        stats[1] = rsqrtf(var + 1e-5f);
    }
    __syncthreads();
    float mean = stats[0], rstd = stats[1];

    float4 gm = *(const float4*)&gamma[tid * 4];
    float4 bt = *(const float4*)&beta[tid * 4];
    float4 r;
    r.x = (v.x - mean) * rstd * gm.x + bt.x;
    r.y = (v.y - mean) * rstd * gm.y + bt.y;
    r.z = (v.z - mean) * rstd * gm.z + bt.z;
    r.w = (v.w - mean) * rstd * gm.w + bt.w;
    *(float4*)&y[tid * 4] = r;
}

extern "C" void kernel_launch(void* const* d_in, const int* in_sizes, int n_in,
                              void* d_out, int out_size)
{
    (void)in_sizes; (void)n_in; (void)out_size;
    const float* queries = (const float*)d_in[0];
    const float* keys    = (const float*)d_in[1];
    const float* values  = (const float*)d_in[2];
    const float* Wq      = (const float*)d_in[3];
    const float* bq      = (const float*)d_in[4];
    const float* Wk      = (const float*)d_in[5];
    const float* bk      = (const float*)d_in[6];
    const float* Wv      = (const float*)d_in[7];
    const float* bv      = (const float*)d_in[8];
    const float* gamma   = (const float*)d_in[9];
    const float* beta    = (const float*)d_in[10];
    float* out = (float*)d_out;

    (void)cudaFuncSetAttribute(proj_kernel,
                               cudaFuncAttributeMaxDynamicSharedMemorySize,
                               PROJ_SMEM_BYTES);

    convx_kernel<<<dim3(2048, 3), 256>>>(queries, keys, values);
    convw_kernel<<<dim3(D_ / 32, HD_ / 32, 3 * H_), dim3(32, 8)>>>(Wq, Wk, Wv);

    dim3 gp(S_ / 128, B_ * H_ / 2, 3);
    proj_kernel<<<gp, 256, PROJ_SMEM_BYTES>>>(bq, bk, bv);

    dim3 ga(S_ / 128, B_ * H_);
    attn_kernel<<<ga, 128>>>();

    ln_kernel<<<B_ * S_, 256>>>(gamma, beta, out);
}

// round 16
// speedup vs baseline: 1.0052x; 1.0052x over previous
#include <cuda_runtime.h>
#include <cuda_fp16.h>
#include <stdint.h>
#include <math.h>

#define B_  2
#define S_  2048
#define D_  1024
#define H_  16
#define HD_ 64

// Scratch (allocation-free rule: __device__ globals).
// g_xh: fp16 copies of queries/keys/values, [which][B][S][D].
// g_wh: fp16 TRANSPOSED weights, [which][H][HD][D]  (n-major rows of k).
// g_q:  fp16 [bh][seq][dim], pre-scaled by 1/sqrt(HD). g_k: fp16 [bh][seq][dim].
// g_v:  fp16 TRANSPOSED [bh][dim][seq] (PV mma wants V as [dim][key]).
__device__ __half g_xh[(size_t)3 * B_ * S_ * D_];
__device__ __half g_wh[(size_t)3 * H_ * D_ * HD_];
__device__ __half g_q[(size_t)B_ * H_ * S_ * HD_];
__device__ __half g_k[(size_t)B_ * H_ * S_ * HD_];
__device__ __half g_v[(size_t)B_ * H_ * S_ * HD_];
__device__ float  g_att[(size_t)B_ * S_ * D_];

__device__ __forceinline__ void mma_f16(float* c, const uint32_t* a, uint32_t b0, uint32_t b1) {
    asm volatile(
        "mma.sync.aligned.m16n8k16.row.col.f32.f16.f16.f32 "
        "{%0,%1,%2,%3}, {%4,%5,%6,%7}, {%8,%9}, {%0,%1,%2,%3};"
        : "+f"(c[0]), "+f"(c[1]), "+f"(c[2]), "+f"(c[3])
        : "r"(a[0]), "r"(a[1]), "r"(a[2]), "r"(a[3]), "r"(b0), "r"(b1));
}

__device__ __forceinline__ uint32_t pack_h2(float lo, float hi) {
    __half2 h = __floats2half2_rn(lo, hi);
    return *(uint32_t*)&h;
}

#define CP_ASYNC16(saddr, gptr) \
    asm volatile("cp.async.cg.shared.global [%0], [%1], 16;\n" :: "r"(saddr), "l"(gptr))
#define CP_COMMIT() asm volatile("cp.async.commit_group;\n" ::: "memory")
#define CP_WAIT0()  asm volatile("cp.async.wait_group 0;\n" ::: "memory")

// ============================================================================
// Pre-convert X (queries/keys/values) to fp16, flat copy. grid (2048, 3).
// ============================================================================
__global__ __launch_bounds__(256) void convx_kernel(
    const float* __restrict__ Xq, const float* __restrict__ Xk, const float* __restrict__ Xv)
{
    const int which = blockIdx.y;
    const float* X = (which == 0) ? Xq : (which == 1) ? Xk : Xv;
    __half* out = g_xh + (size_t)which * B_ * S_ * D_;

    size_t i = ((size_t)blockIdx.x * 256 + threadIdx.x);     // 8 elems each
    const float4* src = (const float4*)X;
    float4 v0 = src[2 * i];
    float4 v1 = src[2 * i + 1];
    uint4 o = make_uint4(pack_h2(v0.x, v0.y), pack_h2(v0.z, v0.w),
                         pack_h2(v1.x, v1.y), pack_h2(v1.z, v1.w));
    ((uint4*)out)[i] = o;
}

// ============================================================================
// Pre-convert + transpose W: [h][k=D][n=HD] fp32 -> [h][n=HD][k=D] fp16.
// Standard smem 32x32 tile transpose. grid (D/32, HD/32, 3*H), block (32,8).
// ============================================================================
__global__ void convw_kernel(
    const float* __restrict__ Wq, const float* __restrict__ Wk, const float* __restrict__ Wv)
{
    const int which = blockIdx.z / H_;
    const int h     = blockIdx.z % H_;
    const float* W = ((which == 0) ? Wq : (which == 1) ? Wk : Wv) + (size_t)h * D_ * HD_;
    __half* out = g_wh + ((size_t)which * H_ + h) * HD_ * D_;

    __shared__ float tile[32][33];
    const int k0 = blockIdx.x * 32;
    const int n0 = blockIdx.y * 32;
    const int tx = threadIdx.x, ty = threadIdx.y;

    #pragma unroll
    for (int i = 0; i < 4; i++)
        tile[ty + i * 8][tx] = W[(size_t)(k0 + ty + i * 8) * HD_ + n0 + tx];
    __syncthreads();
    #pragma unroll
    for (int i = 0; i < 4; i++)
        out[(size_t)(n0 + ty + i * 8) * D_ + k0 + tx] =
            __float2half_rn(tile[tx][ty + i * 8]);
}

// ============================================================================
// fp16 QKV projection: out[b,h,s,:] = fp16((Xh @ Wh[h]^T + bias[h]) * sc)
// grid = (S/128, B*(H/2), 3). Block tile M=128 x N=128 (two heads), 256 thr
// (8 warps, 2Mx4N), warp tile 64x32. m16n8k16 fp16 mma, fp32 accum.
// A: [128m][64k] fp16 stride 36 words; W: [128n][64k] fp16 stride 36 words.
// cp.async double buffer over 64-k chunks (16 chunks).
// Tiles are 128 rows x 8 sixteen-byte granules = 1024 granules -> 4 loader
// iterations of 256 threads (R13 bug: only 2 -> half the tile uninitialized).
// ============================================================================
#define PH_TILE (128 * 36)                       // words, A or W tile
#define PH_A    0
#define PH_W    (2 * PH_TILE)
#define PROJ_SMEM_WORDS (PH_W + 2 * PH_TILE)     // 18432
#define PROJ_SMEM_BYTES (PROJ_SMEM_WORDS * 4)    // 73728

__global__ __launch_bounds__(256) void proj_kernel(
    const float* __restrict__ bq, const float* __restrict__ bk, const float* __restrict__ bv)
{
    extern __shared__ uint32_t dyn[];

    const int which = blockIdx.z;
    const float* bias = (which == 0) ? bq : (which == 1) ? bk : bv;
    __half* out       = (which == 0) ? g_q : (which == 1) ? g_k : g_v;
    const float sc    = (which == 0) ? 0.125f : 1.0f;

    const int mt = blockIdx.x;           // 0..15  (S/128)
    const int bp = blockIdx.y;           // 0..15  (B * H/2)
    const int b  = bp >> 3;
    const int h0 = (bp & 7) * 2;         // first of two heads

    const __half* Xb = g_xh + ((size_t)which * B_ + b) * S_ * D_;
    const __half* Wt = g_wh + (size_t)which * H_ * HD_ * D_;   // [h][n][k]

    const int tid  = threadIdx.x;
    const int warp = tid >> 5;
    const int lane = tid & 31;
    const int g    = lane >> 2;
    const int t    = lane & 3;
    const int wm   = warp >> 2;          // 0..1 -> rows wm*64
    const int wn   = warp & 3;           // 0..3 -> cols wn*32

    const uint32_t sbase = (uint32_t)__cvta_generic_to_shared(dyn);

    float acc[4][4][4];
    #pragma unroll
    for (int ag = 0; ag < 4; ag++)
        #pragma unroll
        for (int j = 0; j < 4; j++)
            #pragma unroll
            for (int r = 0; r < 4; r++)
                acc[ag][j][r] = 0.0f;

    // Loaders: A and W tiles are both 128 rows x 8 granules (16B) = 1024
    auto issue_stage = [&](int k0, int buf) {
        uint32_t adst = sbase + (PH_A + buf * PH_TILE) * 4;
        #pragma unroll
        for (int i = 0; i < 4; i++) {
            int gid = i * 256 + tid;             // 0..1023
            int row = gid >> 3, c = gid & 7;
            CP_ASYNC16(adst + (row * 36) * 4 + c * 16,
                       Xb + (size_t)(mt * 128 + row) * D_ + k0 + c * 8);
        }
        uint32_t wdst = sbase + (PH_W + buf * PH_TILE) * 4;
        #pragma unroll
        for (int i = 0; i < 4; i++) {
            int gid = i * 256 + tid;
            int row = gid >> 3, c = gid & 7;     // row = block-n 0..127
            int h  = h0 + (row >> 6);
            int nn = row & 63;
            CP_ASYNC16(wdst + (row * 36) * 4 + c * 16,
                       Wt + ((size_t)h * HD_ + nn) * D_ + k0 + c * 8);
        }
        CP_COMMIT();
    };

    issue_stage(0, 0);

    const int NK = D_ / 64;                       // 16 chunks
    for (int kc = 0; kc < NK; kc++) {
        const int buf = kc & 1;
        CP_WAIT0();
        __syncthreads();

        if (kc + 1 < NK) issue_stage((kc + 1) * 64, buf ^ 1);

        const uint32_t* As = dyn + PH_A + buf * PH_TILE;   // [128][36]
        const uint32_t* Ws = dyn + PH_W + buf * PH_TILE;   // [128][36]

        #pragma unroll
        for (int kb = 0; kb < 4; kb++) {          // 4 x k16
            uint32_t a[4][4];
            #pragma unroll
            for (int ag = 0; ag < 4; ag++) {
                int m = wm * 64 + ag * 16;
                a[ag][0] = As[(m + g    ) * 36 + kb * 8 + t];
                a[ag][1] = As[(m + g + 8) * 36 + kb * 8 + t];
                a[ag][2] = As[(m + g    ) * 36 + kb * 8 + 4 + t];
                a[ag][3] = As[(m + g + 8) * 36 + kb * 8 + 4 + t];
            }
            uint32_t bb[4][2];
            #pragma unroll
            for (int j = 0; j < 4; j++) {
                int n = wn * 32 + j * 8;
                bb[j][0] = Ws[(n + g) * 36 + kb * 8 + t];
                bb[j][1] = Ws[(n + g) * 36 + kb * 8 + 4 + t];
            }
            #pragma unroll
            for (int ag = 0; ag < 4; ag++)
                #pragma unroll
                for (int j = 0; j < 4; j++)
                    mma_f16(acc[ag][j], a[ag], bb[j][0], bb[j][1]);
        }
        __syncthreads();
    }

    // Epilogue: add bias, scale, round to fp16.
    // Q/K: [bh][seq][dim]; V: transposed [bh][dim][seq].
    #pragma unroll
    for (int ag = 0; ag < 4; ag++) {
        int row = mt * 128 + wm * 64 + ag * 16 + g;
        #pragma unroll
        for (int j = 0; j < 4; j++) {
            int col = wn * 32 + j * 8 + 2 * t;           // 0..126 (even)
            int h   = h0 + (col >> 6);
            int ck  = col & 63;
            const float* bi = bias + (size_t)h * HD_;
            float b0 = bi[ck], b1 = bi[ck + 1];
            float v00 = (acc[ag][j][0] + b0) * sc;
            float v01 = (acc[ag][j][1] + b1) * sc;
            float v10 = (acc[ag][j][2] + b0) * sc;
            float v11 = (acc[ag][j][3] + b1) * sc;
            if (which < 2) {
                __half* Ob = out + (size_t)(b * H_ + h) * S_ * HD_;
                *(uint32_t*)&Ob[(size_t)row * HD_ + ck]       = pack_h2(v00, v01);
                *(uint32_t*)&Ob[(size_t)(row + 8) * HD_ + ck] = pack_h2(v10, v11);
            } else {
                __half* Ob = out + (size_t)(b * H_ + h) * HD_ * S_;
                Ob[(size_t)ck       * S_ + row]     = __float2half_rn(v00);
                Ob[(size_t)(ck + 1) * S_ + row]     = __float2half_rn(v01);
                Ob[(size_t)ck       * S_ + row + 8] = __float2half_rn(v10);
                Ob[(size_t)(ck + 1) * S_ + row + 8] = __float2half_rn(v11);
            }
        }
    }
}

// ============================================================================
// Flash attention, fp16 mma (m16n8k16) — MEASURED at ~150us in the 371us run;
// unchanged. One block = (b,h, 128-row Q tile), 128 threads (4 warps),
// warp owns 32 q-rows. K/V double-buffered cp.async. Static smem 29696 B.
// ============================================================================
#define KS_TILE 1152            // 32*36 words
#define VT_TILE 1280            // 64*20 words
#define KS_OFF  0
#define VT_OFF  (2 * KS_TILE)                   // 2304
#define PS_OFF  (VT_OFF + 2 * VT_TILE)          // 4864
#define ATTN_SMEM_WORDS (PS_OFF + 128 * 20)     // 7424 (29696 B)

__global__ __launch_bounds__(128) void attn_kernel()
{
    __shared__ uint32_t dyn[ATTN_SMEM_WORDS];

    const int qt = blockIdx.x;          // 0..15 (S/128)
    const int bh = blockIdx.y;          // 0..31
    const int b  = bh >> 4;
    const int h  = bh & 15;
    const int q0 = qt * 128;

    const __half* Kg = g_k + (size_t)bh * S_ * HD_;          // [seq][dim]
    const __half* Vt = g_v + (size_t)bh * HD_ * S_;          // [dim][seq]
    const uint32_t* Qu = (const uint32_t*)(g_q + (size_t)bh * S_ * HD_);

    uint32_t* Ps = dyn + PS_OFF;        // [128][20]

    const int tid  = threadIdx.x;
    const int warp = tid >> 5;          // 0..3
    const int lane = tid & 31;
    const int g    = lane >> 2;
    const int t    = lane & 3;
    const int wrow = warp * 32;

    const uint32_t sbase = (uint32_t)__cvta_generic_to_shared(dyn);

    // Q fragments: fp16 pairs, 4 k-chunks of 16 dims
    uint32_t q[2][4][4];
    #pragma unroll
    for (int grp = 0; grp < 2; grp++) {
        int r0 = q0 + wrow + grp * 16 + g;
        #pragma unroll
        for (int kb = 0; kb < 4; kb++) {
            q[grp][kb][0] = Qu[(size_t)r0 * 32 + kb * 8 + t];
            q[grp][kb][1] = Qu[(size_t)(r0 + 8) * 32 + kb * 8 + t];
            q[grp][kb][2] = Qu[(size_t)r0 * 32 + kb * 8 + 4 + t];
            q[grp][kb][3] = Qu[(size_t)(r0 + 8) * 32 + kb * 8 + 4 + t];
        }
    }

    float o[2][8][4];
    #pragma unroll
    for (int grp = 0; grp < 2; grp++)
        #pragma unroll
        for (int j = 0; j < 8; j++)
            #pragma unroll
            for (int r = 0; r < 4; r++) o[grp][j][r] = 0.0f;
    float m[4] = {-INFINITY, -INFINITY, -INFINITY, -INFINITY};
    float l[4] = {0.0f, 0.0f, 0.0f, 0.0f};

    auto load_tile = [&](int kt, int buf) {
        #pragma unroll
        for (int i = 0; i < 2; i++) {
            int gid = i * 128 + tid;
            int row = gid >> 3, c8 = gid & 7;
            CP_ASYNC16(sbase + (KS_OFF + buf * KS_TILE + row * 36) * 4 + c8 * 16,
                       Kg + (size_t)(kt * 32 + row) * HD_ + c8 * 8);
        }
        #pragma unroll
        for (int i = 0; i < 2; i++) {
            int gid = i * 128 + tid;
            int dim = gid >> 2, c8 = gid & 3;
            CP_ASYNC16(sbase + (VT_OFF + buf * VT_TILE + dim * 20) * 4 + c8 * 16,
                       Vt + (size_t)dim * S_ + kt * 32 + c8 * 8);
        }
        CP_COMMIT();
    };

    load_tile(0, 0);

    const int NT = S_ / 32;
    for (int kt = 0; kt < NT; kt++) {
        const int buf = kt & 1;
        CP_WAIT0();
        __syncthreads();                // all warps done with buf^1 from kt-1

        if (kt + 1 < NT) load_tile(kt + 1, buf ^ 1);

        const uint32_t* KsB = dyn + KS_OFF + buf * KS_TILE;   // [32][36]
        const uint32_t* VtB = dyn + VT_OFF + buf * VT_TILE;   // [64][20]

        // S = Q K^T : 32 q-rows x 32 keys per warp (4 k16-chunks)
        float s[2][4][4];
        #pragma unroll
        for (int grp = 0; grp < 2; grp++)
            #pragma unroll
            for (int j = 0; j < 4; j++)
                #pragma unroll
                for (int r = 0; r < 4; r++) s[grp][j][r] = 0.0f;

        #pragma unroll
        for (int kb = 0; kb < 4; kb++) {
            #pragma unroll
            for (int j = 0; j < 4; j++) {
                uint32_t b0 = KsB[(j * 8 + g) * 36 + kb * 8 + t];
                uint32_t b1 = KsB[(j * 8 + g) * 36 + kb * 8 + 4 + t];
                mma_f16(s[0][j], q[0][kb], b0, b1);
                mma_f16(s[1][j], q[1][kb], b0, b1);
            }
        }

        // Online softmax per 16-row group (warp-local shuffles)
        #pragma unroll
        for (int grp = 0; grp < 2; grp++) {
            const int i0 = grp * 2, i1 = grp * 2 + 1;
            float mx0 = -INFINITY, mx1 = -INFINITY;
            #pragma unroll
            for (int j = 0; j < 4; j++) {
                mx0 = fmaxf(mx0, fmaxf(s[grp][j][0], s[grp][j][1]));
                mx1 = fmaxf(mx1, fmaxf(s[grp][j][2], s[grp][j][3]));
            }
            mx0 = fmaxf(mx0, __shfl_xor_sync(0xffffffff, mx0, 1));
            mx0 = fmaxf(mx0, __shfl_xor_sync(0xffffffff, mx0, 2));
            mx1 = fmaxf(mx1, __shfl_xor_sync(0xffffffff, mx1, 1));
            mx1 = fmaxf(mx1, __shfl_xor_sync(0xffffffff, mx1, 2));

            float mn0 = fmaxf(m[i0], mx0), mn1 = fmaxf(m[i1], mx1);
            float al0 = __expf(m[i0] - mn0), al1 = __expf(m[i1] - mn1);
            m[i0] = mn0; m[i1] = mn1;

            float sum0 = 0.0f, sum1 = 0.0f;
            int rp = wrow + grp * 16 + g;
            #pragma unroll
            for (int j = 0; j < 4; j++) {
                float p00 = __expf(s[grp][j][0] - mn0);
                float p01 = __expf(s[grp][j][1] - mn0);
                float p10 = __expf(s[grp][j][2] - mn1);
                float p11 = __expf(s[grp][j][3] - mn1);
                sum0 += p00 + p01;
                sum1 += p10 + p11;
                Ps[rp * 20 + j * 4 + t]       = pack_h2(p00, p01);
                Ps[(rp + 8) * 20 + j * 4 + t] = pack_h2(p10, p11);
            }
            sum0 += __shfl_xor_sync(0xffffffff, sum0, 1);
            sum0 += __shfl_xor_sync(0xffffffff, sum0, 2);
            sum1 += __shfl_xor_sync(0xffffffff, sum1, 1);
            sum1 += __shfl_xor_sync(0xffffffff, sum1, 2);
            l[i0] = l[i0] * al0 + sum0;
            l[i1] = l[i1] * al1 + sum1;

            #pragma unroll
            for (int j = 0; j < 8; j++) {
                o[grp][j][0] *= al0; o[grp][j][1] *= al0;
                o[grp][j][2] *= al1; o[grp][j][3] *= al1;
            }
        }
        __syncwarp();   // Ps rows are warp-private; order writes before reads

        // O += P V : 2 k16-chunks over 32 keys, 8 n-blocks over 64 dims
        #pragma unroll
        for (int kb = 0; kb < 2; kb++) {
            uint32_t a0[4], a1[4];
            {
                int rp = wrow + g;
                a0[0] = Ps[rp * 20 + kb * 8 + t];
                a0[1] = Ps[(rp + 8) * 20 + kb * 8 + t];
                a0[2] = Ps[rp * 20 + kb * 8 + 4 + t];
                a0[3] = Ps[(rp + 8) * 20 + kb * 8 + 4 + t];
                rp = wrow + 16 + g;
                a1[0] = Ps[rp * 20 + kb * 8 + t];
                a1[1] = Ps[(rp + 8) * 20 + kb * 8 + t];
                a1[2] = Ps[rp * 20 + kb * 8 + 4 + t];
                a1[3] = Ps[(rp + 8) * 20 + kb * 8 + 4 + t];
            }
            #pragma unroll
            for (int j = 0; j < 8; j++) {
                uint32_t b0 = VtB[(j * 8 + g) * 20 + kb * 8 + t];
                uint32_t b1 = VtB[(j * 8 + g) * 20 + kb * 8 + 4 + t];
                mma_f16(o[0][j], a0, b0, b1);
                mma_f16(o[1][j], a1, b0, b1);
            }
        }
    }

    // Epilogue: normalize, scatter into [B,S,D] (concat heads), fp32
    float inv[4] = {1.0f / l[0], 1.0f / l[1], 1.0f / l[2], 1.0f / l[3]};
    #pragma unroll
    for (int grp = 0; grp < 2; grp++) {
        #pragma unroll
        for (int j = 0; j < 8; j++) {
            int srow = q0 + wrow + grp * 16 + g;
            int col  = h * HD_ + j * 8 + 2 * t;
            *(float2*)&g_att[((size_t)b * S_ + srow) * D_ + col] =
                make_float2(o[grp][j][0] * inv[grp * 2], o[grp][j][1] * inv[grp * 2]);
            *(float2*)&g_att[((size_t)b * S_ + srow + 8) * D_ + col] =
                make_float2(o[grp][j][2] * inv[grp * 2 + 1], o[grp][j][3] * inv[grp * 2 + 1]);
        }
    }
}

// ============================================================================
// LayerNorm over last dim (1024). One block (256 thr) per row; float4 I/O.
// ============================================================================
__global__ __launch_bounds__(256) void ln_kernel(const float* __restrict__ gamma,
                                                 const float* __restrict__ beta,
                                                 float* __restrict__ out)
{
    const int row = blockIdx.x;
    const float* x = g_att + (size_t)row * D_;
    float*       y = out   + (size_t)row * D_;

    const int tid = threadIdx.x;
    float4 v = *(const float4*)&x[tid * 4];
    float sum = v.x + v.y + v.z + v.w;
    float sq  = v.x * v.x + v.y * v.y + v.z * v.z + v.w * v.w;

    #pragma unroll
    for (int off = 16; off > 0; off >>= 1) {
        sum += __shfl_down_sync(0xffffffff, sum, off);
        sq  += __shfl_down_sync(0xffffffff, sq,  off);
    }
    __shared__ float rs[8], rq[8], stats[2];
    int warp = tid >> 5, lane = tid & 31;
    if (lane == 0) { rs[warp] = sum; rq[warp] = sq; }
    __syncthreads();
    if (tid == 0) {
        float ts = 0.0f, tq = 0.0f;
        #pragma unroll
        for (int i = 0; i < 8; i++) { ts += rs[i]; tq += rq[i]; }
        float mean = ts * (1.0f / D_);
        float var  = tq * (1.0f / D_) - mean * mean;
        stats[0] = mean;
        stats[1] = rsqrtf(var + 1e-5f);
    }
    __syncthreads();
    float mean = stats[0], rstd = stats[1];

    float4 gm = *(const float4*)&gamma[tid * 4];
    float4 bt = *(const float4*)&beta[tid * 4];
    float4 r;
    r.x = (v.x - mean) * rstd * gm.x + bt.x;
    r.y = (v.y - mean) * rstd * gm.y + bt.y;
    r.z = (v.z - mean) * rstd * gm.z + bt.z;
    r.w = (v.w - mean) * rstd * gm.w + bt.w;
    *(float4*)&y[tid * 4] = r;
}

extern "C" void kernel_launch(void* const* d_in, const int* in_sizes, int n_in,
                              void* d_out, int out_size)
{
    (void)in_sizes; (void)n_in; (void)out_size;
    const float* queries = (const float*)d_in[0];
    const float* keys    = (const float*)d_in[1];
    const float* values  = (const float*)d_in[2];
    const float* Wq      = (const float*)d_in[3];
    const float* bq      = (const float*)d_in[4];
    const float* Wk      = (const float*)d_in[5];
    const float* bk      = (const float*)d_in[6];
    const float* Wv      = (const float*)d_in[7];
    const float* bv      = (const float*)d_in[8];
    const float* gamma   = (const float*)d_in[9];
    const float* beta    = (const float*)d_in[10];
    float* out = (float*)d_out;

    (void)cudaFuncSetAttribute(proj_kernel,
                               cudaFuncAttributeMaxDynamicSharedMemorySize,
                               PROJ_SMEM_BYTES);

    convx_kernel<<<dim3(2048, 3), 256>>>(queries, keys, values);
    convw_kernel<<<dim3(D_ / 32, HD_ / 32, 3 * H_), dim3(32, 8)>>>(Wq, Wk, Wv);

    dim3 gp(S_ / 128, B_ * H_ / 2, 3);
    proj_kernel<<<gp, 256, PROJ_SMEM_BYTES>>>(bq, bk, bv);

    dim3 ga(S_ / 128, B_ * H_);
    attn_kernel<<<ga, 128>>>();

    ln_kernel<<<B_ * S_, 256>>>(gamma, beta, out);
}